// round 8
// baseline (speedup 1.0000x reference)
#include <cuda_runtime.h>
#include <cuda_fp16.h>
#include <math.h>

// rbfLayer, round 8: edge-parallel weight precompute (fp16) + lean main kernel.
// K_geom: per edge, geometry + PoU hat decode -> 8 x fp16 weights (wa[4],wr[4])
//         packed in ONE uint4 (16B), coalesced write to 25.6MB L2-resident scratch.
// K_main: 4 lanes/point (lane t owns j-pair {2t,2t+1}). Per edge: one broadcast
//         LDG.128 (weights) + one 8B feature gather; 8 cvt + outer-product
//         accumulate into Z[16 nm] (f32x2). Epilogue contracts vs shared K.

#define PTS_PER_BLOCK 32
#define BLOCK_THREADS 128
#define MAX_E 2000000

typedef unsigned long long u64;

__device__ uint4 g_w[MAX_E];   // per edge: half2(wa0,wa1),(wa2,wa3),(wr0,wr1),(wr2,wr3)

__device__ __forceinline__ u64 pack2(float lo, float hi) {
    u64 r;
    asm("mov.b64 %0, {%1,%2};" : "=l"(r)
        : "r"(__float_as_int(lo)), "r"(__float_as_int(hi)));
    return r;
}
__device__ __forceinline__ void unpack2(u64 v, float& lo, float& hi) {
    int a, b;
    asm("mov.b64 {%0,%1}, %2;" : "=r"(a), "=r"(b) : "l"(v));
    lo = __int_as_float(a); hi = __int_as_float(b);
}
__device__ __forceinline__ u64 fma2(u64 a, u64 b, u64 c) {
    u64 d;
    asm("fma.rn.f32x2 %0, %1, %2, %3;" : "=l"(d) : "l"(a), "l"(b), "l"(c));
    return d;
}
__device__ __forceinline__ u64 mul2(u64 a, u64 b) {
    u64 d;
    asm("mul.rn.f32x2 %0, %1, %2;" : "=l"(d) : "l"(a), "l"(b));
    return d;
}

__device__ __forceinline__ void edge_geom(float dx, float dy,
                                          float& sr, float& sa) {
    float d2 = fmaxf(fmaf(dx, dx, dy * dy), 1e-24f);
    float rinv = rsqrtf(d2);
    sr = d2 * rinv * 1.5f;

    float ax = fabsf(dx), ay = fabsf(dy);
    float mn = fminf(ax, ay);
    float mx = fmaxf(fmaxf(ax, ay), 1e-30f);
    float tq = __fdividef(mn, mx);
    float t2 = tq * tq;
    float pl = -0.0117212f;
    pl = fmaf(pl, t2, 0.05265332f);
    pl = fmaf(pl, t2, -0.11643287f);
    pl = fmaf(pl, t2, 0.19354346f);
    pl = fmaf(pl, t2, -0.33262347f);
    pl = fmaf(pl, t2, 0.99997726f);
    float ang = pl * tq;
    if (ay > ax) ang = 1.5707963267948966f - ang;
    if (dx < 0.0f) ang = 3.141592653589793f - ang;
    float th = ang * 0.3183098861837907f;
    th = (dy < 0.0f) ? -th : th;
    sa = fmaf(th, 2.0f, 2.0f);
}

__device__ __forceinline__ void decode_w(float sr, float sa,
                                         float4& WA, float4& WR) {
    int   kr = (int)sr;
    float fr = sr - (float)kr;
    int   ka = (int)sa;
    float fa = sa - (float)ka;
    int   k0 = ka & 3;
    int   k1 = (ka + 1) & 3;

    WA.x = (k0 == 0) ? (1.0f - fa) : ((k1 == 0) ? fa : 0.0f);
    WA.y = (k0 == 1) ? (1.0f - fa) : ((k1 == 1) ? fa : 0.0f);
    WA.z = (k0 == 2) ? (1.0f - fa) : ((k1 == 2) ? fa : 0.0f);
    WA.w = (k0 == 3) ? (1.0f - fa) : ((k1 == 3) ? fa : 0.0f);

    WR.x = (kr == 0) ? (1.0f - fr) : 0.0f;
    WR.y = (kr == 1) ? (1.0f - fr) : ((kr == 0) ? fr : 0.0f);
    WR.z = (kr == 2) ? (1.0f - fr) : ((kr == 1) ? fr : 0.0f);
    WR.w = (kr == 2) ? fr : 0.0f;
}

__device__ __forceinline__ void accum16(const float4& WA, const float4& WR,
                                        u64 fv2, u64 Zp[16]) {
    u64 t0 = mul2(pack2(WA.x, WA.x), fv2);
    u64 t1 = mul2(pack2(WA.y, WA.y), fv2);
    u64 t2 = mul2(pack2(WA.z, WA.z), fv2);
    u64 t3 = mul2(pack2(WA.w, WA.w), fv2);
    u64 r0 = pack2(WR.x, WR.x);
    u64 r1 = pack2(WR.y, WR.y);
    u64 r2 = pack2(WR.z, WR.z);
    u64 r3 = pack2(WR.w, WR.w);

    Zp[0]  = fma2(r0, t0, Zp[0]);   Zp[1]  = fma2(r0, t1, Zp[1]);
    Zp[2]  = fma2(r0, t2, Zp[2]);   Zp[3]  = fma2(r0, t3, Zp[3]);
    Zp[4]  = fma2(r1, t0, Zp[4]);   Zp[5]  = fma2(r1, t1, Zp[5]);
    Zp[6]  = fma2(r1, t2, Zp[6]);   Zp[7]  = fma2(r1, t3, Zp[7]);
    Zp[8]  = fma2(r2, t0, Zp[8]);   Zp[9]  = fma2(r2, t1, Zp[9]);
    Zp[10] = fma2(r2, t2, Zp[10]);  Zp[11] = fma2(r2, t3, Zp[11]);
    Zp[12] = fma2(r3, t0, Zp[12]);  Zp[13] = fma2(r3, t1, Zp[13]);
    Zp[14] = fma2(r3, t2, Zp[14]);  Zp[15] = fma2(r3, t3, Zp[15]);
}

// ---------------- K_geom: per-edge weights (fp16) ----------------
__global__ __launch_bounds__(256)
void geom_kernel(const float2* __restrict__ pos,
                 const int*    __restrict__ nbrs,
                 int n_pts, int n_edges)
{
    int e = blockIdx.x * 256 + threadIdx.x;
    if (e >= n_edges) return;

    int nb = __ldg(nbrs + e);
    float2 q = __ldg(&pos[nb]);
    int pidx = e >> 4;                 // owner under uniform DEG=16; main kernel
    if (pidx >= n_pts) pidx = n_pts - 1;   // verifies beg==16*point before use
    float2 p = __ldg(&pos[pidx]);

    float sr, sa;
    edge_geom(q.x - p.x, q.y - p.y, sr, sa);
    float4 WA, WR;
    decode_w(sr, sa, WA, WR);

    __half2 h0 = __floats2half2_rn(WA.x, WA.y);
    __half2 h1 = __floats2half2_rn(WA.z, WA.w);
    __half2 h2 = __floats2half2_rn(WR.x, WR.y);
    __half2 h3 = __floats2half2_rn(WR.z, WR.w);
    uint4 w;
    w.x = *(unsigned*)&h0;
    w.y = *(unsigned*)&h1;
    w.z = *(unsigned*)&h2;
    w.w = *(unsigned*)&h3;
    g_w[e] = w;
}

// unpack one fp16 weight record + accumulate
__device__ __forceinline__ void process_edge(const uint4& W, const float2& F,
                                             u64 Zp[16]) {
    float2 a01 = __half22float2(*(const __half2*)&W.x);
    float2 a23 = __half22float2(*(const __half2*)&W.y);
    float2 r01 = __half22float2(*(const __half2*)&W.z);
    float2 r23 = __half22float2(*(const __half2*)&W.w);
    float4 WA = make_float4(a01.x, a01.y, a23.x, a23.y);
    float4 WR = make_float4(r01.x, r01.y, r23.x, r23.y);
    accum16(WA, WR, pack2(F.x, F.y), Zp);
}

// ---------------- K_main ----------------
__global__ __launch_bounds__(BLOCK_THREADS, 6)
void rbf_layer_kernel(const float2* __restrict__ pos,
                      const float*  __restrict__ feat,
                      const float*  __restrict__ kern,
                      const int*    __restrict__ nbrs,
                      const int*    __restrict__ rsp,
                      float*        __restrict__ out,
                      int n_pts, int use_w)
{
    // sk2[(i*8+nm2)*4 + t] = { pack(K[i][2t][2nm2],   K[i][2t+1][2nm2]),
    //                          pack(K[i][2t][2nm2+1], K[i][2t+1][2nm2+1]) }
    __shared__ ulonglong2 sk2[8 * 8 * 4];
    int tid = threadIdx.x;

    for (int idx = tid; idx < 256; idx += BLOCK_THREADS) {
        int tt  = idx & 3;
        int nm2 = (idx >> 2) & 7;
        int i   = idx >> 5;
        int n0 = 2 * nm2, n1 = 2 * nm2 + 1;
        ulonglong2 v;
        v.x = pack2(kern[(i * 8 + 2 * tt)     * 16 + n0],
                    kern[(i * 8 + 2 * tt + 1) * 16 + n0]);
        v.y = pack2(kern[(i * 8 + 2 * tt)     * 16 + n1],
                    kern[(i * 8 + 2 * tt + 1) * 16 + n1]);
        sk2[idx] = v;
    }
    __syncthreads();

    int gid   = blockIdx.x * BLOCK_THREADS + tid;
    int point = gid >> 2;
    int t     = tid & 3;

    bool valid = (point < n_pts);
    int pclamp = valid ? point : 0;

    int beg = valid ? __ldg(rsp + pclamp)     : 0;
    int end = valid ? __ldg(rsp + pclamp + 1) : 0;
    int cnt = end - beg;

    bool fast = valid && use_w && (cnt == 16) && (beg == (point << 4));

    const float2* f2 = (const float2*)feat;

    u64 Zp[16];
    #pragma unroll
    for (int k = 0; k < 16; ++k) Zp[k] = 0ull;

    if (fast) {
        const uint4* wp = g_w + beg;
        const int4* nb4 = (const int4*)(nbrs + beg);
        int4 q0 = __ldg(nb4 + 0);
        int4 q1 = __ldg(nb4 + 1);
        int4 q2 = __ldg(nb4 + 2);
        int4 q3 = __ldg(nb4 + 3);
        int nb[16] = {q0.x, q0.y, q0.z, q0.w, q1.x, q1.y, q1.z, q1.w,
                      q2.x, q2.y, q2.z, q2.w, q3.x, q3.y, q3.z, q3.w};

        // software pipeline, groups of 2 edges, one group ahead
        uint4  Wa = __ldg(wp + 0), Wb = __ldg(wp + 1);
        float2 Fa = __ldg(&f2[(unsigned)nb[0] * 4 + t]);
        float2 Fb = __ldg(&f2[(unsigned)nb[1] * 4 + t]);

        #pragma unroll
        for (int g = 0; g < 8; ++g) {
            uint4 Wc, Wd; float2 Fc, Fd;
            if (g < 7) {
                Wc = __ldg(wp + 2 * g + 2);
                Wd = __ldg(wp + 2 * g + 3);
                Fc = __ldg(&f2[(unsigned)nb[2 * g + 2] * 4 + t]);
                Fd = __ldg(&f2[(unsigned)nb[2 * g + 3] * 4 + t]);
            }
            process_edge(Wa, Fa, Zp);
            process_edge(Wb, Fb, Zp);
            Wa = Wc; Wb = Wd; Fa = Fc; Fb = Fd;
        }
    } else if (valid) {
        const float2 pp = __ldg(&pos[pclamp]);
        for (int e = beg; e < end; ++e) {
            int nb = __ldg(nbrs + e);
            float2 q = __ldg(&pos[nb]);
            float sr, sa;
            edge_geom(q.x - pp.x, q.y - pp.y, sr, sa);
            float4 WA, WR;
            decode_w(sr, sa, WA, WR);
            float2 fv = __ldg(&f2[nb * 4 + t]);
            accum16(WA, WR, pack2(fv.x, fv.y), Zp);
        }
    }

    // ---- Epilogue ----
    float pr[8];
    #pragma unroll
    for (int i = 0; i < 8; ++i) {
        u64 acc = 0ull;
        #pragma unroll
        for (int nm2 = 0; nm2 < 8; ++nm2) {
            ulonglong2 kk = sk2[(i * 8 + nm2) * 4 + t];
            acc = fma2(kk.x, Zp[2 * nm2],     acc);
            acc = fma2(kk.y, Zp[2 * nm2 + 1], acc);
        }
        float lo, hi;
        unpack2(acc, lo, hi);
        pr[i] = lo + hi;
    }

    #pragma unroll
    for (int i = 0; i < 8; ++i) {
        pr[i] += __shfl_xor_sync(0xffffffffu, pr[i], 1);
        pr[i] += __shfl_xor_sync(0xffffffffu, pr[i], 2);
    }

    if (valid) {
        float o0 = pr[0], o1 = pr[4];
        if (t == 1) { o0 = pr[1]; o1 = pr[5]; }
        if (t == 2) { o0 = pr[2]; o1 = pr[6]; }
        if (t == 3) { o0 = pr[3]; o1 = pr[7]; }
        out[point * 8 + t]     = o0;
        out[point * 8 + 4 + t] = o1;
    }
}

extern "C" void kernel_launch(void* const* d_in, const int* in_sizes, int n_in,
                              void* d_out, int out_size)
{
    const float* positions  = (const float*)d_in[0];
    const float* features   = (const float*)d_in[1];
    const float* kernel     = (const float*)d_in[2];
    const int*   neighbors  = (const int*)d_in[3];
    const int*   row_splits = (const int*)d_in[4];
    float*       out        = (float*)d_out;

    int n_pts   = in_sizes[0] / 2;
    int n_edges = in_sizes[3];
    int use_w   = (n_edges <= MAX_E) ? 1 : 0;

    if (use_w) {
        geom_kernel<<<(n_edges + 255) / 256, 256>>>(
            (const float2*)positions, neighbors, n_pts, n_edges);
    }

    int blocks = (n_pts + PTS_PER_BLOCK - 1) / PTS_PER_BLOCK;
    rbf_layer_kernel<<<blocks, BLOCK_THREADS>>>(
        (const float2*)positions, features, kernel, neighbors, row_splits,
        out, n_pts, use_w);
}

// round 9
// speedup vs baseline: 1.1913x; 1.1913x over previous
#include <cuda_runtime.h>
#include <math.h>

// rbfLayer, round 9: fused, 8B/edge smem staging of raw (sr,sa).
// Phase 1: 128 threads x 4 edges -> geometry once per edge, (sr,sa) to smem.
// Phase 2: 4 lanes/point (lane t owns j-pair {2t,2t+1}); per edge one LDS.64-pair
//          (broadcast, conflict-free), inline PoU decode, one 8B feat gather,
//          f32x2 outer-product accumulate into Z[16]. Epilogue vs shared K.

#define PTS_PER_BLOCK 32
#define BLOCK_THREADS 128
#define SSW_STRIDE 18          // float2 slots per point row (16 + 2 pad)

typedef unsigned long long u64;

__device__ __forceinline__ u64 pack2(float lo, float hi) {
    u64 r;
    asm("mov.b64 %0, {%1,%2};" : "=l"(r)
        : "r"(__float_as_int(lo)), "r"(__float_as_int(hi)));
    return r;
}
__device__ __forceinline__ void unpack2(u64 v, float& lo, float& hi) {
    int a, b;
    asm("mov.b64 {%0,%1}, %2;" : "=r"(a), "=r"(b) : "l"(v));
    lo = __int_as_float(a); hi = __int_as_float(b);
}
__device__ __forceinline__ u64 fma2(u64 a, u64 b, u64 c) {
    u64 d;
    asm("fma.rn.f32x2 %0, %1, %2, %3;" : "=l"(d) : "l"(a), "l"(b), "l"(c));
    return d;
}
__device__ __forceinline__ u64 mul2(u64 a, u64 b) {
    u64 d;
    asm("mul.rn.f32x2 %0, %1, %2;" : "=l"(d) : "l"(a), "l"(b));
    return d;
}

__device__ __forceinline__ void edge_geom(float dx, float dy,
                                          float& sr, float& sa) {
    float d2 = fmaxf(fmaf(dx, dx, dy * dy), 1e-24f);
    float rinv = rsqrtf(d2);
    sr = d2 * rinv * 1.5f;

    float ax = fabsf(dx), ay = fabsf(dy);
    float mn = fminf(ax, ay);
    float mx = fmaxf(fmaxf(ax, ay), 1e-30f);
    float tq = __fdividef(mn, mx);
    float t2 = tq * tq;
    float pl = -0.0117212f;
    pl = fmaf(pl, t2, 0.05265332f);
    pl = fmaf(pl, t2, -0.11643287f);
    pl = fmaf(pl, t2, 0.19354346f);
    pl = fmaf(pl, t2, -0.33262347f);
    pl = fmaf(pl, t2, 0.99997726f);
    float ang = pl * tq;
    if (ay > ax) ang = 1.5707963267948966f - ang;
    if (dx < 0.0f) ang = 3.141592653589793f - ang;
    float th = ang * 0.3183098861837907f;
    th = (dy < 0.0f) ? -th : th;
    sa = fmaf(th, 2.0f, 2.0f);
}

__device__ __forceinline__ void decode_w(float sr, float sa,
                                         float4& WA, float4& WR) {
    int   kr = (int)sr;
    float fr = sr - (float)kr;
    int   ka = (int)sa;
    float fa = sa - (float)ka;
    int   k0 = ka & 3;
    int   k1 = (ka + 1) & 3;

    WA.x = (k0 == 0) ? (1.0f - fa) : ((k1 == 0) ? fa : 0.0f);
    WA.y = (k0 == 1) ? (1.0f - fa) : ((k1 == 1) ? fa : 0.0f);
    WA.z = (k0 == 2) ? (1.0f - fa) : ((k1 == 2) ? fa : 0.0f);
    WA.w = (k0 == 3) ? (1.0f - fa) : ((k1 == 3) ? fa : 0.0f);

    WR.x = (kr == 0) ? (1.0f - fr) : 0.0f;
    WR.y = (kr == 1) ? (1.0f - fr) : ((kr == 0) ? fr : 0.0f);
    WR.z = (kr == 2) ? (1.0f - fr) : ((kr == 1) ? fr : 0.0f);
    WR.w = (kr == 2) ? fr : 0.0f;
}

__device__ __forceinline__ void accum16(const float4& WA, const float4& WR,
                                        u64 fv2, u64 Zp[16]) {
    u64 t0 = mul2(pack2(WA.x, WA.x), fv2);
    u64 t1 = mul2(pack2(WA.y, WA.y), fv2);
    u64 t2 = mul2(pack2(WA.z, WA.z), fv2);
    u64 t3 = mul2(pack2(WA.w, WA.w), fv2);
    u64 r0 = pack2(WR.x, WR.x);
    u64 r1 = pack2(WR.y, WR.y);
    u64 r2 = pack2(WR.z, WR.z);
    u64 r3 = pack2(WR.w, WR.w);

    Zp[0]  = fma2(r0, t0, Zp[0]);   Zp[1]  = fma2(r0, t1, Zp[1]);
    Zp[2]  = fma2(r0, t2, Zp[2]);   Zp[3]  = fma2(r0, t3, Zp[3]);
    Zp[4]  = fma2(r1, t0, Zp[4]);   Zp[5]  = fma2(r1, t1, Zp[5]);
    Zp[6]  = fma2(r1, t2, Zp[6]);   Zp[7]  = fma2(r1, t3, Zp[7]);
    Zp[8]  = fma2(r2, t0, Zp[8]);   Zp[9]  = fma2(r2, t1, Zp[9]);
    Zp[10] = fma2(r2, t2, Zp[10]);  Zp[11] = fma2(r2, t3, Zp[11]);
    Zp[12] = fma2(r3, t0, Zp[12]);  Zp[13] = fma2(r3, t1, Zp[13]);
    Zp[14] = fma2(r3, t2, Zp[14]);  Zp[15] = fma2(r3, t3, Zp[15]);
}

__global__ __launch_bounds__(BLOCK_THREADS, 6)
void rbf_layer_kernel(const float2* __restrict__ pos,
                      const float*  __restrict__ feat,
                      const float*  __restrict__ kern,
                      const int*    __restrict__ nbrs,
                      const int*    __restrict__ rsp,
                      float*        __restrict__ out,
                      int n_pts, int n_edges)
{
    __shared__ ulonglong2 sk2[8 * 8 * 4];               // 4 KB epilogue K
    __shared__ float2 ssw[PTS_PER_BLOCK * SSW_STRIDE];  // 4.6 KB (sr,sa)

    int tid = threadIdx.x;

    for (int idx = tid; idx < 256; idx += BLOCK_THREADS) {
        int tt  = idx & 3;
        int nm2 = (idx >> 2) & 7;
        int i   = idx >> 5;
        int n0 = 2 * nm2, n1 = 2 * nm2 + 1;
        ulonglong2 v;
        v.x = pack2(kern[(i * 8 + 2 * tt)     * 16 + n0],
                    kern[(i * 8 + 2 * tt + 1) * 16 + n0]);
        v.y = pack2(kern[(i * 8 + 2 * tt)     * 16 + n1],
                    kern[(i * 8 + 2 * tt + 1) * 16 + n1]);
        sk2[idx] = v;
    }

    int p0 = blockIdx.x * PTS_PER_BLOCK;

    // ---- Phase 1: geometry for 4 edges/thread, assuming uniform rows ----
    // (valid exactly for points with beg==16*point && cnt==16; phase 2 checks)
    {
        int ptl = tid >> 2;                 // local point 0..31
        int k4  = (tid & 3) * 4;            // first of this thread's 4 edges
        int e0  = p0 * 16 + ptl * 16 + k4;  // assumed global edge index
        int4 nbq;
        if (e0 + 3 < n_edges) {
            nbq = __ldg((const int4*)(nbrs + e0));
        } else {
            nbq.x = (e0 + 0 < n_edges) ? __ldg(nbrs + e0 + 0) : 0;
            nbq.y = (e0 + 1 < n_edges) ? __ldg(nbrs + e0 + 1) : 0;
            nbq.z = (e0 + 2 < n_edges) ? __ldg(nbrs + e0 + 2) : 0;
            nbq.w = (e0 + 3 < n_edges) ? __ldg(nbrs + e0 + 3) : 0;
        }
        int pidx = p0 + ptl;
        float2 pp = __ldg(&pos[(pidx < n_pts) ? pidx : 0]);
        float2 q0 = __ldg(&pos[nbq.x]);
        float2 q1 = __ldg(&pos[nbq.y]);
        float2 q2 = __ldg(&pos[nbq.z]);
        float2 q3 = __ldg(&pos[nbq.w]);

        float2* dst = &ssw[ptl * SSW_STRIDE + k4];
        float sr, sa;
        edge_geom(q0.x - pp.x, q0.y - pp.y, sr, sa); dst[0] = make_float2(sr, sa);
        edge_geom(q1.x - pp.x, q1.y - pp.y, sr, sa); dst[1] = make_float2(sr, sa);
        edge_geom(q2.x - pp.x, q2.y - pp.y, sr, sa); dst[2] = make_float2(sr, sa);
        edge_geom(q3.x - pp.x, q3.y - pp.y, sr, sa); dst[3] = make_float2(sr, sa);
    }
    __syncthreads();

    // ---- Phase 2 ----
    int gid   = blockIdx.x * BLOCK_THREADS + tid;
    int point = gid >> 2;
    int t     = tid & 3;

    bool valid = (point < n_pts);
    int pclamp = valid ? point : 0;

    int beg = valid ? __ldg(rsp + pclamp)     : 0;
    int end = valid ? __ldg(rsp + pclamp + 1) : 0;
    int cnt = end - beg;

    bool fast = valid && (cnt == 16) && (beg == (point << 4));

    const float2* f2 = (const float2*)feat;

    u64 Zp[16];
    #pragma unroll
    for (int k = 0; k < 16; ++k) Zp[k] = 0ull;

    if (fast) {
        int lpt = point - p0;
        const float2* swp = &ssw[lpt * SSW_STRIDE];
        const int4* nb4 = (const int4*)(nbrs + beg);
        int4 q0 = __ldg(nb4 + 0);
        int4 q1 = __ldg(nb4 + 1);
        int4 q2 = __ldg(nb4 + 2);
        int4 q3 = __ldg(nb4 + 3);

        // pipeline: features for group g+1 prefetched while processing g
        float2 Fa = __ldg(&f2[(unsigned)q0.x * 4 + t]);
        float2 Fb = __ldg(&f2[(unsigned)q0.y * 4 + t]);
        float2 Fc = __ldg(&f2[(unsigned)q0.z * 4 + t]);
        float2 Fd = __ldg(&f2[(unsigned)q0.w * 4 + t]);

        #pragma unroll
        for (int g = 0; g < 4; ++g) {
            float2 Na, Nb, Nc, Nd;
            if (g < 3) {
                int4 qn = (g == 0) ? q1 : (g == 1) ? q2 : q3;
                Na = __ldg(&f2[(unsigned)qn.x * 4 + t]);
                Nb = __ldg(&f2[(unsigned)qn.y * 4 + t]);
                Nc = __ldg(&f2[(unsigned)qn.z * 4 + t]);
                Nd = __ldg(&f2[(unsigned)qn.w * 4 + t]);
            }
            // (sr,sa) for this group's 4 edges: 2x LDS.128, broadcast in group
            float4 s01 = *(const float4*)(swp + g * 4);
            float4 s23 = *(const float4*)(swp + g * 4 + 2);

            float4 WA, WR;
            decode_w(s01.x, s01.y, WA, WR); accum16(WA, WR, pack2(Fa.x, Fa.y), Zp);
            decode_w(s01.z, s01.w, WA, WR); accum16(WA, WR, pack2(Fb.x, Fb.y), Zp);
            decode_w(s23.x, s23.y, WA, WR); accum16(WA, WR, pack2(Fc.x, Fc.y), Zp);
            decode_w(s23.z, s23.w, WA, WR); accum16(WA, WR, pack2(Fd.x, Fd.y), Zp);
            Fa = Na; Fb = Nb; Fc = Nc; Fd = Nd;
        }
    } else if (valid) {
        const float2 pp = __ldg(&pos[pclamp]);
        for (int e = beg; e < end; ++e) {
            int nb = __ldg(nbrs + e);
            float2 q = __ldg(&pos[nb]);
            float sr, sa;
            edge_geom(q.x - pp.x, q.y - pp.y, sr, sa);
            float4 WA, WR;
            decode_w(sr, sa, WA, WR);
            float2 fv = __ldg(&f2[nb * 4 + t]);
            accum16(WA, WR, pack2(fv.x, fv.y), Zp);
        }
    }

    // ---- Epilogue ----
    float pr[8];
    #pragma unroll
    for (int i = 0; i < 8; ++i) {
        u64 acc = 0ull;
        #pragma unroll
        for (int nm2 = 0; nm2 < 8; ++nm2) {
            ulonglong2 kk = sk2[(i * 8 + nm2) * 4 + t];
            acc = fma2(kk.x, Zp[2 * nm2],     acc);
            acc = fma2(kk.y, Zp[2 * nm2 + 1], acc);
        }
        float lo, hi;
        unpack2(acc, lo, hi);
        pr[i] = lo + hi;
    }

    #pragma unroll
    for (int i = 0; i < 8; ++i) {
        pr[i] += __shfl_xor_sync(0xffffffffu, pr[i], 1);
        pr[i] += __shfl_xor_sync(0xffffffffu, pr[i], 2);
    }

    if (valid) {
        float o0 = pr[0], o1 = pr[4];
        if (t == 1) { o0 = pr[1]; o1 = pr[5]; }
        if (t == 2) { o0 = pr[2]; o1 = pr[6]; }
        if (t == 3) { o0 = pr[3]; o1 = pr[7]; }
        out[point * 8 + t]     = o0;
        out[point * 8 + 4 + t] = o1;
    }
}

extern "C" void kernel_launch(void* const* d_in, const int* in_sizes, int n_in,
                              void* d_out, int out_size)
{
    const float* positions  = (const float*)d_in[0];
    const float* features   = (const float*)d_in[1];
    const float* kernel     = (const float*)d_in[2];
    const int*   neighbors  = (const int*)d_in[3];
    const int*   row_splits = (const int*)d_in[4];
    float*       out        = (float*)d_out;

    int n_pts   = in_sizes[0] / 2;
    int n_edges = in_sizes[3];

    int blocks = (n_pts + PTS_PER_BLOCK - 1) / PTS_PER_BLOCK;
    rbf_layer_kernel<<<blocks, BLOCK_THREADS>>>(
        (const float2*)positions, features, kernel, neighbors, row_splits,
        out, n_pts, n_edges);
}

// round 10
// speedup vs baseline: 1.2207x; 1.0246x over previous
#include <cuda_runtime.h>
#include <math.h>

// rbfLayer, round 10: R9 structure + occupancy push (<=64 regs, 8 blocks/SM).
// Phase 1: 1 thread per (point, edge-quad): coalesced nbr int4 -> smem;
//          pos gathers + geometry once per edge -> (sr,sa) smem (8B/edge).
// Phase 2: 4 lanes/point (lane t owns j-pair {2t,2t+1}); per 4-edge group:
//          nbr quad via LDS.128, 4 independent feat gathers (MLP4),
//          weights via 2x LDS.128, inline PoU decode, f32x2 accumulate.
// No cross-group software pipeline: occupancy (8 warps/SMSP) hides L2 latency.

#define PTS_PER_BLOCK 32
#define BLOCK_THREADS 128
#define SSW_STRIDE 18          // float2 per point row (16 + 2 pad)

typedef unsigned long long u64;

__device__ __forceinline__ u64 pack2(float lo, float hi) {
    u64 r;
    asm("mov.b64 %0, {%1,%2};" : "=l"(r)
        : "r"(__float_as_int(lo)), "r"(__float_as_int(hi)));
    return r;
}
__device__ __forceinline__ void unpack2(u64 v, float& lo, float& hi) {
    int a, b;
    asm("mov.b64 {%0,%1}, %2;" : "=r"(a), "=r"(b) : "l"(v));
    lo = __int_as_float(a); hi = __int_as_float(b);
}
__device__ __forceinline__ u64 fma2(u64 a, u64 b, u64 c) {
    u64 d;
    asm("fma.rn.f32x2 %0, %1, %2, %3;" : "=l"(d) : "l"(a), "l"(b), "l"(c));
    return d;
}
__device__ __forceinline__ u64 mul2(u64 a, u64 b) {
    u64 d;
    asm("mul.rn.f32x2 %0, %1, %2;" : "=l"(d) : "l"(a), "l"(b));
    return d;
}

__device__ __forceinline__ void edge_geom(float dx, float dy,
                                          float& sr, float& sa) {
    float d2 = fmaxf(fmaf(dx, dx, dy * dy), 1e-24f);
    float rinv = rsqrtf(d2);
    sr = d2 * rinv * 1.5f;

    float ax = fabsf(dx), ay = fabsf(dy);
    float mn = fminf(ax, ay);
    float mx = fmaxf(fmaxf(ax, ay), 1e-30f);
    float tq = __fdividef(mn, mx);
    float t2 = tq * tq;
    float pl = -0.0117212f;
    pl = fmaf(pl, t2, 0.05265332f);
    pl = fmaf(pl, t2, -0.11643287f);
    pl = fmaf(pl, t2, 0.19354346f);
    pl = fmaf(pl, t2, -0.33262347f);
    pl = fmaf(pl, t2, 0.99997726f);
    float ang = pl * tq;
    if (ay > ax) ang = 1.5707963267948966f - ang;
    if (dx < 0.0f) ang = 3.141592653589793f - ang;
    float th = ang * 0.3183098861837907f;
    th = (dy < 0.0f) ? -th : th;
    sa = fmaf(th, 2.0f, 2.0f);
}

__device__ __forceinline__ void decode_w(float sr, float sa,
                                         float4& WA, float4& WR) {
    int   kr = (int)sr;
    float fr = sr - (float)kr;
    int   ka = (int)sa;
    float fa = sa - (float)ka;
    int   k0 = ka & 3;
    int   k1 = (ka + 1) & 3;

    WA.x = (k0 == 0) ? (1.0f - fa) : ((k1 == 0) ? fa : 0.0f);
    WA.y = (k0 == 1) ? (1.0f - fa) : ((k1 == 1) ? fa : 0.0f);
    WA.z = (k0 == 2) ? (1.0f - fa) : ((k1 == 2) ? fa : 0.0f);
    WA.w = (k0 == 3) ? (1.0f - fa) : ((k1 == 3) ? fa : 0.0f);

    WR.x = (kr == 0) ? (1.0f - fr) : 0.0f;
    WR.y = (kr == 1) ? (1.0f - fr) : ((kr == 0) ? fr : 0.0f);
    WR.z = (kr == 2) ? (1.0f - fr) : ((kr == 1) ? fr : 0.0f);
    WR.w = (kr == 2) ? fr : 0.0f;
}

__device__ __forceinline__ void accum16(const float4& WA, const float4& WR,
                                        u64 fv2, u64 Zp[16]) {
    u64 t0 = mul2(pack2(WA.x, WA.x), fv2);
    u64 t1 = mul2(pack2(WA.y, WA.y), fv2);
    u64 t2 = mul2(pack2(WA.z, WA.z), fv2);
    u64 t3 = mul2(pack2(WA.w, WA.w), fv2);
    u64 r0 = pack2(WR.x, WR.x);
    u64 r1 = pack2(WR.y, WR.y);
    u64 r2 = pack2(WR.z, WR.z);
    u64 r3 = pack2(WR.w, WR.w);

    Zp[0]  = fma2(r0, t0, Zp[0]);   Zp[1]  = fma2(r0, t1, Zp[1]);
    Zp[2]  = fma2(r0, t2, Zp[2]);   Zp[3]  = fma2(r0, t3, Zp[3]);
    Zp[4]  = fma2(r1, t0, Zp[4]);   Zp[5]  = fma2(r1, t1, Zp[5]);
    Zp[6]  = fma2(r1, t2, Zp[6]);   Zp[7]  = fma2(r1, t3, Zp[7]);
    Zp[8]  = fma2(r2, t0, Zp[8]);   Zp[9]  = fma2(r2, t1, Zp[9]);
    Zp[10] = fma2(r2, t2, Zp[10]);  Zp[11] = fma2(r2, t3, Zp[11]);
    Zp[12] = fma2(r3, t0, Zp[12]);  Zp[13] = fma2(r3, t1, Zp[13]);
    Zp[14] = fma2(r3, t2, Zp[14]);  Zp[15] = fma2(r3, t3, Zp[15]);
}

__global__ __launch_bounds__(BLOCK_THREADS, 8)
void rbf_layer_kernel(const float2* __restrict__ pos,
                      const float*  __restrict__ feat,
                      const float*  __restrict__ kern,
                      const int*    __restrict__ nbrs,
                      const int*    __restrict__ rsp,
                      float*        __restrict__ out,
                      int n_pts, int n_edges)
{
    __shared__ ulonglong2 sk2[8 * 8 * 4];               // 4 KB epilogue K
    __shared__ float2 ssw[PTS_PER_BLOCK * SSW_STRIDE];  // 4.6 KB (sr,sa)
    __shared__ int4   snbr[PTS_PER_BLOCK * 5];          // padded nbr quads

    int tid = threadIdx.x;

    for (int idx = tid; idx < 256; idx += BLOCK_THREADS) {
        int tt  = idx & 3;
        int nm2 = (idx >> 2) & 7;
        int i   = idx >> 5;
        int n0 = 2 * nm2, n1 = 2 * nm2 + 1;
        ulonglong2 v;
        v.x = pack2(kern[(i * 8 + 2 * tt)     * 16 + n0],
                    kern[(i * 8 + 2 * tt + 1) * 16 + n0]);
        v.y = pack2(kern[(i * 8 + 2 * tt)     * 16 + n1],
                    kern[(i * 8 + 2 * tt + 1) * 16 + n1]);
        sk2[idx] = v;
    }

    int p0 = blockIdx.x * PTS_PER_BLOCK;

    // ---- Phase 1: nbr quads + geometry -> smem (uniform-row assumption;
    //      phase 2 verifies beg==16*point && cnt==16 before using it) ----
    {
        int ptl = tid >> 2;                 // local point 0..31
        int g   = tid & 3;                  // edge quad 0..3
        int e0  = (p0 + ptl) * 16 + g * 4;
        int4 nbq;
        if (e0 + 3 < n_edges) {
            nbq = __ldg((const int4*)(nbrs + e0));
        } else {
            nbq.x = (e0 + 0 < n_edges) ? __ldg(nbrs + e0 + 0) : 0;
            nbq.y = (e0 + 1 < n_edges) ? __ldg(nbrs + e0 + 1) : 0;
            nbq.z = (e0 + 2 < n_edges) ? __ldg(nbrs + e0 + 2) : 0;
            nbq.w = (e0 + 3 < n_edges) ? __ldg(nbrs + e0 + 3) : 0;
        }
        snbr[ptl * 5 + g] = nbq;

        int pidx = p0 + ptl;
        float2 pp = __ldg(&pos[(pidx < n_pts) ? pidx : 0]);
        float2 q0 = __ldg(&pos[nbq.x]);
        float2 q1 = __ldg(&pos[nbq.y]);
        float2 q2 = __ldg(&pos[nbq.z]);
        float2 q3 = __ldg(&pos[nbq.w]);

        float2* dst = &ssw[ptl * SSW_STRIDE + g * 4];
        float sr, sa;
        edge_geom(q0.x - pp.x, q0.y - pp.y, sr, sa); dst[0] = make_float2(sr, sa);
        edge_geom(q1.x - pp.x, q1.y - pp.y, sr, sa); dst[1] = make_float2(sr, sa);
        edge_geom(q2.x - pp.x, q2.y - pp.y, sr, sa); dst[2] = make_float2(sr, sa);
        edge_geom(q3.x - pp.x, q3.y - pp.y, sr, sa); dst[3] = make_float2(sr, sa);
    }
    __syncthreads();

    // ---- Phase 2 ----
    int point = p0 + (tid >> 2);
    int t     = tid & 3;

    bool valid = (point < n_pts);
    int pclamp = valid ? point : 0;

    int beg = valid ? __ldg(rsp + pclamp)     : 0;
    int end = valid ? __ldg(rsp + pclamp + 1) : 0;
    int cnt = end - beg;

    bool fast = valid && (cnt == 16) && (beg == (point << 4));

    const float2* f2 = (const float2*)feat;

    u64 Zp[16];
    #pragma unroll
    for (int k = 0; k < 16; ++k) Zp[k] = 0ull;

    if (fast) {
        int lpt = point - p0;
        const float2* swp = &ssw[lpt * SSW_STRIDE];

        #pragma unroll
        for (int g = 0; g < 4; ++g) {
            int4 nbq = snbr[lpt * 5 + g];
            // 4 independent gathers (MLP 4); occupancy hides the rest
            float2 Fa = __ldg(&f2[(unsigned)nbq.x * 4 + t]);
            float2 Fb = __ldg(&f2[(unsigned)nbq.y * 4 + t]);
            float2 Fc = __ldg(&f2[(unsigned)nbq.z * 4 + t]);
            float2 Fd = __ldg(&f2[(unsigned)nbq.w * 4 + t]);

            float4 WA, WR;
            {
                float4 s01 = *(const float4*)(swp + g * 4);
                decode_w(s01.x, s01.y, WA, WR); accum16(WA, WR, pack2(Fa.x, Fa.y), Zp);
                decode_w(s01.z, s01.w, WA, WR); accum16(WA, WR, pack2(Fb.x, Fb.y), Zp);
            }
            {
                float4 s23 = *(const float4*)(swp + g * 4 + 2);
                decode_w(s23.x, s23.y, WA, WR); accum16(WA, WR, pack2(Fc.x, Fc.y), Zp);
                decode_w(s23.z, s23.w, WA, WR); accum16(WA, WR, pack2(Fd.x, Fd.y), Zp);
            }
        }
    } else if (valid) {
        const float2 pp = __ldg(&pos[pclamp]);
        for (int e = beg; e < end; ++e) {
            int nb = __ldg(nbrs + e);
            float2 q = __ldg(&pos[nb]);
            float sr, sa;
            edge_geom(q.x - pp.x, q.y - pp.y, sr, sa);
            float4 WA, WR;
            decode_w(sr, sa, WA, WR);
            float2 fv = __ldg(&f2[nb * 4 + t]);
            accum16(WA, WR, pack2(fv.x, fv.y), Zp);
        }
    }

    // ---- Epilogue ----
    float pr[8];
    #pragma unroll
    for (int i = 0; i < 8; ++i) {
        u64 acc = 0ull;
        #pragma unroll
        for (int nm2 = 0; nm2 < 8; ++nm2) {
            ulonglong2 kk = sk2[(i * 8 + nm2) * 4 + t];
            acc = fma2(kk.x, Zp[2 * nm2],     acc);
            acc = fma2(kk.y, Zp[2 * nm2 + 1], acc);
        }
        float lo, hi;
        unpack2(acc, lo, hi);
        pr[i] = lo + hi;
    }

    #pragma unroll
    for (int i = 0; i < 8; ++i) {
        pr[i] += __shfl_xor_sync(0xffffffffu, pr[i], 1);
        pr[i] += __shfl_xor_sync(0xffffffffu, pr[i], 2);
    }

    if (valid) {
        float o0 = pr[0], o1 = pr[4];
        if (t == 1) { o0 = pr[1]; o1 = pr[5]; }
        if (t == 2) { o0 = pr[2]; o1 = pr[6]; }
        if (t == 3) { o0 = pr[3]; o1 = pr[7]; }
        out[point * 8 + t]     = o0;
        out[point * 8 + 4 + t] = o1;
    }
}

extern "C" void kernel_launch(void* const* d_in, const int* in_sizes, int n_in,
                              void* d_out, int out_size)
{
    const float* positions  = (const float*)d_in[0];
    const float* features   = (const float*)d_in[1];
    const float* kernel     = (const float*)d_in[2];
    const int*   neighbors  = (const int*)d_in[3];
    const int*   row_splits = (const int*)d_in[4];
    float*       out        = (float*)d_out;

    int n_pts   = in_sizes[0] / 2;
    int n_edges = in_sizes[3];

    int blocks = (n_pts + PTS_PER_BLOCK - 1) / PTS_PER_BLOCK;
    rbf_layer_kernel<<<blocks, BLOCK_THREADS>>>(
        (const float2*)positions, features, kernel, neighbors, row_splits,
        out, n_pts, n_edges);
}